// round 16
// baseline (speedup 1.0000x reference)
#include <cuda_runtime.h>
#include <cuda_bf16.h>
#include <cuda_fp16.h>
#include <cstdint>
#include <cstddef>

#define N_NODES 50000
#define N_EDGES 400000
#define H 256
#define D_IN 128
#define NH (N_NODES * H)
#define NH512 (N_NODES * 512)

// ---------------- scratch (static device globals; no allocations) ------------
__device__ float g_isd[N_NODES];
__device__ float g_big1[NH512];                  // hw512(fp16) / UV(fp16) storage
__device__ float g_big2[NH512];                  // agg512 fp32
__device__ __align__(16) uint16_t g_a512hi[NH512];   // fp16 bits
__device__ __align__(16) uint16_t g_a512lo[NH512];
__device__ __align__(16) uint16_t g_acthi[NH];   // hc fp16 hi
__device__ __align__(16) uint16_t g_actlo[NH];
__device__ __align__(16) uint16_t g_xhi[N_NODES * D_IN];   // (Â x) bf16 hi
__device__ __align__(16) uint16_t g_xlo[N_NODES * D_IN];
__device__ __align__(16) uint16_t g_e1hi[(size_t)N_EDGES * H];   // fp16 bits
__device__ __align__(16) uint16_t g_e1lo[(size_t)N_EDGES * H];
__device__ __align__(16) uint16_t g_e2hi[(size_t)N_EDGES * H];
__device__ __align__(16) uint16_t g_e2lo[(size_t)N_EDGES * H];
// weight pool (element offsets), B stored [K, N] row-major
#define OFF_WN1 0        // [128,512] bf16 hi/lo
#define OFF_WN2 65536    // [256,512] fp16 single
#define OFF_WN3 196608   // [256,512] fp16 single
#define OFF_WUV 327680   // [256,512] fp16 single
#define OFF_WC2 458752   // [256,256] fp16 single
#define OFF_WC3 524288   // [256,128] fp16 single
#define OFF_WC4 557056   // [128,64]  fp16 single
#define W_TOTAL 565248
__device__ __align__(16) uint16_t g_whi[W_TOTAL];
__device__ __align__(16) uint16_t g_wlo[W_TOTAL];
__device__ float g_sum[512];
__device__ float g_sq[512];
__device__ float g_mean[512];
__device__ float g_rstd[512];
__device__ float g_bias512[512];
// CSR
__device__ int g_rowstart[N_NODES + 1];
__device__ int g_cursor[N_NODES];
__device__ int g_csr_src[N_EDGES];
__device__ float g_csr_w[N_EDGES];

// ---------------- helpers -----------------------------------------------------
__device__ __forceinline__ void bf16_split(float v, uint16_t& hi, uint16_t& lo) {
    __nv_bfloat16 h = __float2bfloat16_rn(v);
    float r = v - __bfloat162float(h);
    __nv_bfloat16 l = __float2bfloat16_rn(r);
    hi = *reinterpret_cast<uint16_t*>(&h);
    lo = *reinterpret_cast<uint16_t*>(&l);
}
__device__ __forceinline__ void fp16_split(float v, uint16_t& hi, uint16_t& lo) {
    __half h = __float2half_rn(v);
    float r = v - __half2float(h);
    __half l = __float2half_rn(r);
    hi = *reinterpret_cast<uint16_t*>(&h);
    lo = *reinterpret_cast<uint16_t*>(&l);
}
__device__ __forceinline__ uint32_t smem_u32(const void* p) {
    uint32_t a;
    asm("{ .reg .u64 t; cvta.to.shared.u64 t, %1; cvt.u32.u64 %0, t; }" : "=r"(a) : "l"(p));
    return a;
}
__device__ __forceinline__ void cpasync16(uint32_t dst, const void* src, bool ok) {
    int sz = ok ? 16 : 0;
    asm volatile("cp.async.cg.shared.global [%0], [%1], 16, %2;"
                 :: "r"(dst), "l"(src), "r"(sz));
}
__device__ __forceinline__ void cpasync_commit() {
    asm volatile("cp.async.commit_group;" ::: "memory");
}
__device__ __forceinline__ void cpasync_wait0() { asm volatile("cp.async.wait_group 0;" ::: "memory"); }
__device__ __forceinline__ void cpasync_wait1() { asm volatile("cp.async.wait_group 1;" ::: "memory"); }
// convert 8 packed halves (uint4) to 8 floats
__device__ __forceinline__ void h8_to_f8(const uint4& v, float* f) {
    const __half2* p = reinterpret_cast<const __half2*>(&v);
#pragma unroll
    for (int i = 0; i < 4; i++) {
        float2 t = __half22float2(p[i]);
        f[2 * i] = t.x;
        f[2 * i + 1] = t.y;
    }
}

// ---------------- degree / CSR -------------------------------------------------
__global__ void deg_init(float* d, int n) {
    int i = blockIdx.x * blockDim.x + threadIdx.x;
    if (i < n) d[i] = 1.0f;
}
__global__ void deg_count(const int* __restrict__ dst, float* d, int e) {
    int i = blockIdx.x * blockDim.x + threadIdx.x;
    if (i < e) atomicAdd(&d[dst[i]], 1.0f);
}
__global__ void deg_fin(float* d, int n) {
    int i = blockIdx.x * blockDim.x + threadIdx.x;
    if (i < n) d[i] = rsqrtf(d[i]);
}
__global__ void zero_int(int* p, int n) {
    int i = blockIdx.x * blockDim.x + threadIdx.x;
    if (i < n) p[i] = 0;
}
__global__ void count_int(const int* __restrict__ dst, int* cnt, int e) {
    int i = blockIdx.x * blockDim.x + threadIdx.x;
    if (i < e) atomicAdd(&cnt[dst[i]], 1);
}
__global__ void scan_deg(const int* __restrict__ cnt, int* __restrict__ rowstart) {
    __shared__ int ssum[1024];
    const int CHUNK = (N_NODES + 1023) / 1024;
    int t = threadIdx.x;
    int c0 = t * CHUNK;
    int s = 0;
    for (int i = 0; i < CHUNK; i++) {
        int idx = c0 + i;
        if (idx < N_NODES) s += cnt[idx];
    }
    ssum[t] = s;
    __syncthreads();
    for (int off = 1; off < 1024; off <<= 1) {
        int v = (t >= off) ? ssum[t - off] : 0;
        __syncthreads();
        ssum[t] += v;
        __syncthreads();
    }
    int run = (t > 0) ? ssum[t - 1] : 0;
    for (int i = 0; i < CHUNK; i++) {
        int idx = c0 + i;
        if (idx < N_NODES) {
            rowstart[idx] = run;
            run += cnt[idx];
        }
    }
    if (t == 1023) rowstart[N_NODES] = run;
}
__global__ void csr_fill(const int* __restrict__ src, const int* __restrict__ dst,
                         const int* __restrict__ rowstart, int* cursor,
                         const float* __restrict__ isd, int* __restrict__ csr_src,
                         float* __restrict__ csr_w)
{
    int e = blockIdx.x * blockDim.x + threadIdx.x;
    if (e < N_EDGES) {
        int d = dst[e], s = src[e];
        int pos = rowstart[d] + atomicAdd(&cursor[d], 1);
        csr_src[pos] = s;
        csr_w[pos] = isd[s] * isd[d];
    }
}

// ---------------- conversion / packing ----------------------------------------
__global__ void convert_fp16(const float* __restrict__ in, uint16_t* __restrict__ hi, int n)
{
    int i = blockIdx.x * blockDim.x + threadIdx.x;
    if (i < n) {
        __half h = __float2half_rn(in[i]);
        hi[i] = *reinterpret_cast<uint16_t*>(&h);
    }
}
// pack two [K,256] weights side by side -> [K,512] (bf16 split)
__global__ void pack2(const float* __restrict__ Wa, const float* __restrict__ Wb,
                      uint16_t* __restrict__ hi, uint16_t* __restrict__ lo, int total)
{
    int idx = blockIdx.x * blockDim.x + threadIdx.x;
    if (idx < total) {
        int k = idx >> 9, n = idx & 511;
        float v = (n < 256) ? Wa[k * 256 + n] : Wb[k * 256 + (n - 256)];
        uint16_t h, l;
        bf16_split(v, h, l);
        hi[idx] = h;
        lo[idx] = l;
    }
}
// pack two [K,256] weights side by side -> [K,512] fp16 single
__global__ void pack2_fp16(const float* __restrict__ Wa, const float* __restrict__ Wb,
                           uint16_t* __restrict__ hi, int total)
{
    int idx = blockIdx.x * blockDim.x + threadIdx.x;
    if (idx < total) {
        int k = idx >> 9, n = idx & 511;
        float v = (n < 256) ? Wa[k * 256 + n] : Wb[k * 256 + (n - 256)];
        __half h = __float2half_rn(v);
        hi[idx] = *reinterpret_cast<uint16_t*>(&h);
    }
}
// pack [Wc1a | Wc1b] (stacked in K) -> [256, 512] fp16 single
__global__ void pack_wuv_fp16(const float* __restrict__ Wc1, uint16_t* __restrict__ hi)
{
    int idx = blockIdx.x * blockDim.x + threadIdx.x;
    if (idx < 256 * 512) {
        int k = idx >> 9, n = idx & 511;
        float v = (n < 256) ? Wc1[k * 256 + n] : Wc1[(256 + k) * 256 + (n - 256)];
        __half h = __float2half_rn(v);
        hi[idx] = *reinterpret_cast<uint16_t*>(&h);
    }
}
__global__ void pack_bias512(const float* __restrict__ b1, const float* __restrict__ b2,
                             float* __restrict__ out)
{
    int i = blockIdx.x * 256 + threadIdx.x;
    if (i < 512) out[i] = (i < 256) ? b1[i] : b2[i - 256];
}

// ---------------- tensor-core GEMM (cp.async, CTA 128x64, occ 3) --------------
// FP16MODE=0: bf16x3 (A hi/lo, B hi/lo). FP16MODE=1: fp16x2 (A hi/lo, B single).
// outMode: 0 fp32 C; 1 split hi/lo C; 2 fused final 64->2; 3 fp16-single C.
#define AS_STRIDE 40
#define BS_STR 72
#define A_BYTES (128 * AS_STRIDE * 2)     // 10240
#define B_BYTES (32 * BS_STR * 2)         // 4608
#define NSTAGE 2

__device__ __forceinline__ void ldmA(uint32_t r[4], uint32_t base, int row0, int ks, int lane) {
    int mat = lane >> 3, rr = lane & 7;
    int row = row0 + (mat & 1) * 8 + rr;
    int k = ks + (mat >> 1) * 8;
    uint32_t addr = base + (uint32_t)(row * AS_STRIDE + k) * 2u;
    asm volatile("ldmatrix.sync.aligned.m8n8.x4.shared.b16 {%0,%1,%2,%3}, [%4];"
                 : "=r"(r[0]), "=r"(r[1]), "=r"(r[2]), "=r"(r[3]) : "r"(addr));
}
__device__ __forceinline__ void ldmB(uint32_t r[4], uint32_t base, int ks, int n0, int lane) {
    int part = lane >> 3, rr = lane & 7;
    int k = ks + (part & 1) * 8 + rr;
    int n = n0 + (part >> 1) * 8;
    uint32_t addr = base + (uint32_t)(k * BS_STR + n) * 2u;
    asm volatile("ldmatrix.sync.aligned.m8n8.x4.trans.shared.b16 {%0,%1,%2,%3}, [%4];"
                 : "=r"(r[0]), "=r"(r[1]), "=r"(r[2]), "=r"(r[3]) : "r"(addr));
}
__device__ __forceinline__ void mma_bf16(float d[4], const uint32_t a[4], const uint32_t b[2]) {
    asm volatile("mma.sync.aligned.m16n8k16.row.col.f32.bf16.bf16.f32 "
                 "{%0,%1,%2,%3},{%4,%5,%6,%7},{%8,%9},{%0,%1,%2,%3};"
                 : "+f"(d[0]), "+f"(d[1]), "+f"(d[2]), "+f"(d[3])
                 : "r"(a[0]), "r"(a[1]), "r"(a[2]), "r"(a[3]), "r"(b[0]), "r"(b[1]));
}
__device__ __forceinline__ void mma_fp16(float d[4], const uint32_t a[4], const uint32_t b[2]) {
    asm volatile("mma.sync.aligned.m16n8k16.row.col.f32.f16.f16.f32 "
                 "{%0,%1,%2,%3},{%4,%5,%6,%7},{%8,%9},{%0,%1,%2,%3};"
                 : "+f"(d[0]), "+f"(d[1]), "+f"(d[2]), "+f"(d[3])
                 : "r"(a[0]), "r"(a[1]), "r"(a[2]), "r"(a[3]), "r"(b[0]), "r"(b[1]));
}

template <int FP16MODE>
__global__ __launch_bounds__(256, 3)
void gemm_tc(const uint16_t* __restrict__ Ahi, const uint16_t* __restrict__ Alo,
             int lda, int splitHalf,
             const uint16_t* __restrict__ Bhi, const uint16_t* __restrict__ Blo,
             const float* __restrict__ bias, float* __restrict__ Cf,
             uint16_t* __restrict__ Chi, uint16_t* __restrict__ Clo,
             const float* __restrict__ W5, const float* __restrict__ b5,
             int M, int Nc, int K, int doRelu, int outMode)
{
    constexpr int STAGE_BYTES = 2 * A_BYTES + (FP16MODE ? 1 : 2) * B_BYTES;
    extern __shared__ __align__(16) uint8_t dynsmem[];
    uint32_t sbase = smem_u32(dynsmem);
    __shared__ float s_w5[128];
    __shared__ float s_part[4][32][2];

    int tid = threadIdx.x;
    int lane = tid & 31;
    int wid = tid >> 5;
    int wm = (wid & 3) * 32;
    int wn = (wid >> 2) * 32;
    int m0 = blockIdx.y * 128;
    int n0 = blockIdx.x * 64;
    int koff = (splitHalf && n0 >= 256) ? 256 : 0;

    if (outMode == 2 && tid < 128) s_w5[tid] = W5[tid];

    float d[2][4][4];
#pragma unroll
    for (int mt = 0; mt < 2; mt++)
#pragma unroll
        for (int nt = 0; nt < 4; nt++)
#pragma unroll
            for (int q = 0; q < 4; q++) d[mt][nt][q] = 0.f;

    int KT = K / 32;

    auto load_stage = [&](int s, int kc) {
        uint32_t base = sbase + (uint32_t)s * STAGE_BYTES;
#pragma unroll
        for (int q = 0; q < 2; q++) {
            int ch = tid + q * 256;
            int row = ch >> 2, c16 = ch & 3;
            bool ok = (m0 + row) < M;
            size_t go = (size_t)(m0 + (ok ? row : 0)) * lda + koff + kc + c16 * 8;
            uint32_t dA = base + (uint32_t)(row * (AS_STRIDE * 2) + c16 * 16);
            cpasync16(dA, Ahi + go, ok);
            cpasync16(dA + A_BYTES, Alo + go, ok);
        }
        {
            int kr = tid >> 3, nn = (tid & 7) * 8;
            bool ok = (n0 + nn) < Nc;
            size_t go = (size_t)(kc + kr) * Nc + (ok ? (n0 + nn) : 0);
            uint32_t dB = base + 2 * A_BYTES + (uint32_t)(kr * (BS_STR * 2) + nn * 2);
            cpasync16(dB, Bhi + go, ok);
            if (!FP16MODE) cpasync16(dB + B_BYTES, Blo + go, ok);
        }
        cpasync_commit();
    };

    load_stage(0, 0);
    load_stage(1, 32);   // KT >= 4 for all our GEMMs

    for (int kt = 0; kt < KT; kt++) {
        int s = kt & 1;
        if (kt + 1 < KT) cpasync_wait1(); else cpasync_wait0();
        __syncthreads();

        uint32_t stg = sbase + (uint32_t)s * STAGE_BYTES;
        uint32_t sAhi = stg;
        uint32_t sAlo = stg + A_BYTES;
        uint32_t sBhi = stg + 2 * A_BYTES;
        uint32_t sBlo = stg + 2 * A_BYTES + B_BYTES;   // unused in fp16 mode

#pragma unroll
        for (int ks = 0; ks < 32; ks += 16) {
            uint32_t AH[2][4], AL[2][4];
#pragma unroll
            for (int mt = 0; mt < 2; mt++) {
                ldmA(AH[mt], sAhi, wm + mt * 16, ks, lane);
                ldmA(AL[mt], sAlo, wm + mt * 16, ks, lane);
            }
#pragma unroll
            for (int jp = 0; jp < 2; jp++) {
                uint32_t bh[4];
                ldmB(bh, sBhi, ks, wn + jp * 16, lane);
                if (FP16MODE) {
#pragma unroll
                    for (int mt = 0; mt < 2; mt++) {
                        mma_fp16(d[mt][2 * jp], AH[mt], bh);
                        mma_fp16(d[mt][2 * jp + 1], AH[mt], bh + 2);
                        mma_fp16(d[mt][2 * jp], AL[mt], bh);
                        mma_fp16(d[mt][2 * jp + 1], AL[mt], bh + 2);
                    }
                } else {
                    uint32_t bl[4];
                    ldmB(bl, sBlo, ks, wn + jp * 16, lane);
#pragma unroll
                    for (int mt = 0; mt < 2; mt++) {
                        mma_bf16(d[mt][2 * jp], AH[mt], bh);
                        mma_bf16(d[mt][2 * jp + 1], AH[mt], bh + 2);
                        mma_bf16(d[mt][2 * jp], AL[mt], bh);
                        mma_bf16(d[mt][2 * jp + 1], AL[mt], bh + 2);
                        mma_bf16(d[mt][2 * jp], AH[mt], bl);
                        mma_bf16(d[mt][2 * jp + 1], AH[mt], bl + 2);
                    }
                }
            }
        }

        if (kt + 2 < KT) {
            __syncthreads();            // all warps done reading stage s
            load_stage(s, (kt + 2) * 32);
        }
    }

    int g = lane >> 2, tg = lane & 3;

    if (outMode == 2) {
        // fused final: relu(v)+bias (bc4) then dot with W5[64,2]; M % 128 == 0.
        float p[2][2][2];
#pragma unroll
        for (int mt = 0; mt < 2; mt++)
#pragma unroll
            for (int hh = 0; hh < 2; hh++) { p[mt][hh][0] = 0.f; p[mt][hh][1] = 0.f; }
#pragma unroll
        for (int mt = 0; mt < 2; mt++)
#pragma unroll
            for (int hh = 0; hh < 2; hh++)
#pragma unroll
                for (int nt = 0; nt < 4; nt++) {
                    int col = wn + nt * 8 + tg * 2;
                    float v0 = fmaxf(d[mt][nt][hh * 2 + 0] + bias[col], 0.f);
                    float v1 = fmaxf(d[mt][nt][hh * 2 + 1] + bias[col + 1], 0.f);
                    p[mt][hh][0] += v0 * s_w5[col * 2] + v1 * s_w5[(col + 1) * 2];
                    p[mt][hh][1] += v0 * s_w5[col * 2 + 1] + v1 * s_w5[(col + 1) * 2 + 1];
                }
#pragma unroll
        for (int mt = 0; mt < 2; mt++)
#pragma unroll
            for (int hh = 0; hh < 2; hh++)
#pragma unroll
                for (int o = 0; o < 2; o++) {
                    float v = p[mt][hh][o];
                    v += __shfl_xor_sync(0xffffffffu, v, 1);
                    v += __shfl_xor_sync(0xffffffffu, v, 2);
                    p[mt][hh][o] = v;
                }
        int wmb = wid & 3;
        if ((wid >> 2) == 1 && tg == 0) {
#pragma unroll
            for (int mt = 0; mt < 2; mt++)
#pragma unroll
                for (int hh = 0; hh < 2; hh++) {
                    int rib = mt * 16 + hh * 8 + g;
                    s_part[wmb][rib][0] = p[mt][hh][0];
                    s_part[wmb][rib][1] = p[mt][hh][1];
                }
        }
        __syncthreads();
        if ((wid >> 2) == 0 && tg == 0) {
            float bb0 = b5[0], bb1 = b5[1];
#pragma unroll
            for (int mt = 0; mt < 2; mt++)
#pragma unroll
                for (int hh = 0; hh < 2; hh++) {
                    int rib = mt * 16 + hh * 8 + g;
                    int row = m0 + wm + rib;
                    float a0 = p[mt][hh][0] + s_part[wmb][rib][0] + bb0;
                    float a1 = p[mt][hh][1] + s_part[wmb][rib][1] + bb1;
                    *(float2*)&Cf[(size_t)row * 2] = make_float2(a0, a1);
                }
        }
        return;
    }

#pragma unroll
    for (int mt = 0; mt < 2; mt++) {
#pragma unroll
        for (int hh = 0; hh < 2; hh++) {
            int row = m0 + wm + mt * 16 + g + hh * 8;
            if (row >= M) continue;
#pragma unroll
            for (int nt = 0; nt < 4; nt++) {
                int col = n0 + wn + nt * 8 + tg * 2;
                if (col >= Nc) continue;
                float v0 = d[mt][nt][hh * 2 + 0];
                float v1 = d[mt][nt][hh * 2 + 1];
                if (bias) { v0 += bias[col]; v1 += bias[col + 1]; }
                if (doRelu) { v0 = fmaxf(v0, 0.f); v1 = fmaxf(v1, 0.f); }
                size_t o = (size_t)row * Nc + col;
                if (outMode == 0) {
                    *(float2*)&Cf[o] = make_float2(v0, v1);
                } else if (outMode == 3) {
                    __half h0 = __float2half_rn(v0);
                    __half h1 = __float2half_rn(v1);
                    *(uint32_t*)&Chi[o] = (uint32_t)*(uint16_t*)&h0 |
                                          ((uint32_t)*(uint16_t*)&h1 << 16);
                } else {
                    uint16_t h0, l0, h1, l1;
                    if (FP16MODE) { fp16_split(v0, h0, l0); fp16_split(v1, h1, l1); }
                    else          { bf16_split(v0, h0, l0); bf16_split(v1, h1, l1); }
                    *(uint32_t*)&Chi[o] = (uint32_t)h0 | ((uint32_t)h1 << 16);
                    *(uint32_t*)&Clo[o] = (uint32_t)l0 | ((uint32_t)l1 << 16);
                }
            }
        }
    }
}

// ---------------- layer-1: 128-wide CSR gather of x -> bf16 split -------------
__global__ __launch_bounds__(256)
void gcn_gather_x(const float* __restrict__ x, const int* __restrict__ rowstart,
                  const int* __restrict__ csr_src, const float* __restrict__ csr_w,
                  const float* __restrict__ isd, uint16_t* __restrict__ outhi,
                  uint16_t* __restrict__ outlo)
{
    int w = (blockIdx.x * 256 + threadIdx.x) >> 5;
    int lane = threadIdx.x & 31;
    if (w >= N_NODES) return;
    float s = isd[w];
    float s2 = s * s;
    float4 v = *(const float4*)(x + (size_t)w * D_IN + lane * 4);
    float acc[4] = {v.x * s2, v.y * s2, v.z * s2, v.w * s2};
    int st = rowstart[w], en = rowstart[w + 1];
    for (int base = st; base < en; base += 32) {
        int n = en - base;
        if (n > 32) n = 32;
        int mys = (lane < n) ? csr_src[base + lane] : 0;
        float myw = (lane < n) ? csr_w[base + lane] : 0.f;
        for (int t = 0; t < n; t++) {
            int sidx = __shfl_sync(0xffffffffu, mys, t);
            float wt = __shfl_sync(0xffffffffu, myw, t);
            float4 hv = *(const float4*)(x + (size_t)sidx * D_IN + lane * 4);
            acc[0] += hv.x * wt;
            acc[1] += hv.y * wt;
            acc[2] += hv.z * wt;
            acc[3] += hv.w * wt;
        }
    }
    uint16_t h[4], l[4];
#pragma unroll
    for (int j = 0; j < 4; j++) bf16_split(acc[j], h[j], l[j]);
    size_t o = (size_t)w * D_IN + lane * 4;
    *(uint2*)&outhi[o] = make_uint2((uint32_t)h[0] | ((uint32_t)h[1] << 16),
                                    (uint32_t)h[2] | ((uint32_t)h[3] << 16));
    *(uint2*)&outlo[o] = make_uint2((uint32_t)l[0] | ((uint32_t)l[1] << 16),
                                    (uint32_t)l[2] | ((uint32_t)l[3] << 16));
}

// standalone BN stats over a [N,512] fp32 buffer
__global__ void bn_stats512(const float* __restrict__ h)
{
    int tid = threadIdx.x;
    int node0 = blockIdx.x * 8;
    float s0 = 0.f, q0 = 0.f, s1 = 0.f, q1 = 0.f;
#pragma unroll
    for (int r = 0; r < 8; r++) {
        int node = node0 + r;
        if (node < N_NODES) {
            float v0 = h[(size_t)node * 512 + tid];
            float v1 = h[(size_t)node * 512 + tid + 256];
            s0 += v0; q0 += v0 * v0;
            s1 += v1; q1 += v1 * v1;
        }
    }
    atomicAdd(&g_sum[tid], s0);
    atomicAdd(&g_sq[tid], q0);
    atomicAdd(&g_sum[tid + 256], s1);
    atomicAdd(&g_sq[tid + 256], q1);
}

// ---------------- GCN aggregation: fp16-row 512-wide CSR gather + BN stats ----
__global__ __launch_bounds__(256)
void gcn_gather512h(const __half* __restrict__ hw, const int* __restrict__ rowstart,
                    const int* __restrict__ csr_src, const float* __restrict__ csr_w,
                    const float* __restrict__ isd, const float* __restrict__ b1,
                    const float* __restrict__ b2, float* __restrict__ agg)
{
    int tid = threadIdx.x;
    int w = (blockIdx.x * 256 + tid) >> 5;
    int lane = tid & 31;
    if (w < N_NODES) {
        float s = isd[w];
        float s2 = s * s;
        const __half* hrow = hw + (size_t)w * 512;
        int c0 = lane * 16;   // this lane's 16 contiguous columns
        float acc[16];
        {
            float f[16];
            h8_to_f8(*(const uint4*)(hrow + c0), f);
            h8_to_f8(*(const uint4*)(hrow + c0 + 8), f + 8);
#pragma unroll
            for (int j = 0; j < 16; j++) {
                int c = c0 + j;
                float bias = (c < 256) ? b1[c] : b2[c - 256];
                acc[j] = f[j] * s2 + bias;
            }
        }
        int st = rowstart[w], en = rowstart[w + 1];
        for (int base = st; base < en; base += 32) {
            int n = en - base;
            if (n > 32) n = 32;
            int mys = (lane < n) ? csr_src[base + lane] : 0;
            float myw = (lane < n) ? csr_w[base + lane] : 0.f;
            for (int t = 0; t < n; t++) {
                int sidx = __shfl_sync(0xffffffffu, mys, t);
                float wt = __shfl_sync(0xffffffffu, myw, t);
                const __half* hs = hw + (size_t)sidx * 512 + c0;
                float f[16];
                h8_to_f8(*(const uint4*)hs, f);
                h8_to_f8(*(const uint4*)(hs + 8), f + 8);
#pragma unroll
                for (int j = 0; j < 16; j++) acc[j] += f[j] * wt;
            }
        }
        float* arow = agg + (size_t)w * 512 + c0;
#pragma unroll
        for (int q = 0; q < 4; q++)
            *(float4*)&arow[q * 4] = make_float4(acc[q * 4], acc[q * 4 + 1],
                                                 acc[q * 4 + 2], acc[q * 4 + 3]);
    }
    __syncthreads();
    int node0 = (blockIdx.x * 256) >> 5;
    float s0 = 0.f, q0 = 0.f, s1 = 0.f, q1 = 0.f;
#pragma unroll
    for (int r = 0; r < 8; r++) {
        int node = node0 + r;
        if (node < N_NODES) {
            float v0 = agg[(size_t)node * 512 + tid];
            float v1 = agg[(size_t)node * 512 + tid + 256];
            s0 += v0; q0 += v0 * v0;
            s1 += v1; q1 += v1 * v1;
        }
    }
    atomicAdd(&g_sum[tid], s0);
    atomicAdd(&g_sq[tid], q0);
    atomicAdd(&g_sum[tid + 256], s1);
    atomicAdd(&g_sq[tid + 256], q1);
}

// ---------------- BatchNorm ----------------------------------------------------
__global__ void bn_zero512() {
    int c = threadIdx.x;
    g_sum[c] = 0.0f;
    g_sq[c] = 0.0f;
}
__global__ void bn_final512() {
    int c = threadIdx.x;
    float m = g_sum[c] * (1.0f / N_NODES);
    float v = g_sq[c] * (1.0f / N_NODES) - m * m;
    g_mean[c] = m;
    g_rstd[c] = rsqrtf(v + 1e-5f);
}
// BN + ReLU -> fp16 hi/lo split (feeds fp16x2 node GEMMs)
__global__ void bn_apply_split512(const float* __restrict__ h, const float* __restrict__ g,
                                  const float* __restrict__ be, uint16_t* __restrict__ hi,
                                  uint16_t* __restrict__ lo, int n2)
{
    int i2 = blockIdx.x * blockDim.x + threadIdx.x;
    if (i2 < n2) {
        int i = i2 * 2;
        int c0 = i & 511, c1 = c0 + 1;
        float v0 = fmaxf(g[c0 & 255] * (h[i] - g_mean[c0]) * g_rstd[c0] + be[c0 & 255], 0.f);
        float v1 = fmaxf(g[c1 & 255] * (h[i + 1] - g_mean[c1]) * g_rstd[c1] + be[c1 & 255], 0.f);
        uint16_t h0, l0, h1, l1;
        fp16_split(v0, h0, l0);
        fp16_split(v1, h1, l1);
        *(uint32_t*)&hi[i] = (uint32_t)h0 | ((uint32_t)h1 << 16);
        *(uint32_t*)&lo[i] = (uint32_t)l0 | ((uint32_t)l1 << 16);
    }
}
// layer3: BN both halves + add -> hc fp16 hi/lo (feeds fp16x2 UV GEMM)
__global__ void bn_add_convert(const float* __restrict__ h, const float* __restrict__ g,
                               const float* __restrict__ be, uint16_t* __restrict__ hi,
                               uint16_t* __restrict__ lo, int n2)
{
    int i2 = blockIdx.x * blockDim.x + threadIdx.x;
    if (i2 < n2) {
        int i = i2 * 2;
        int r = i >> 8;
        int c0 = i & 255, c1 = c0 + 1;
        const float* row = h + (size_t)r * 512;
        float L0 = fmaxf(g[c0] * (row[c0] - g_mean[c0]) * g_rstd[c0] + be[c0], 0.f);
        float R0 = fmaxf(g[c0] * (row[c0 + 256] - g_mean[c0 + 256]) * g_rstd[c0 + 256] + be[c0], 0.f);
        float L1 = fmaxf(g[c1] * (row[c1] - g_mean[c1]) * g_rstd[c1] + be[c1], 0.f);
        float R1 = fmaxf(g[c1] * (row[c1 + 256] - g_mean[c1 + 256]) * g_rstd[c1 + 256] + be[c1], 0.f);
        float v0 = L0 + R0;
        float v1 = L1 + R1;
        uint16_t h0, l0, h1, l1;
        fp16_split(v0, h0, l0);
        fp16_split(v1, h1, l1);
        *(uint32_t*)&hi[i] = (uint32_t)h0 | ((uint32_t)h1 << 16);
        *(uint32_t*)&lo[i] = (uint32_t)l0 | ((uint32_t)l1 << 16);
    }
}

// ---------------- fused edge-MLP layer 1 (fp16 UV in, fp16 hi/lo out) ---------
__global__ __launch_bounds__(256)
void edge_l1(const __half* __restrict__ UV, const float* __restrict__ attr,
             const float* __restrict__ Wattr, const float* __restrict__ bias,
             const int* __restrict__ src, const int* __restrict__ dst,
             uint16_t* __restrict__ outhi, uint16_t* __restrict__ outlo)
{
    __shared__ float Ws[8 * 256];
    __shared__ float bs[256];
    for (int i = threadIdx.x; i < 8 * 256; i += 256) Ws[i] = Wattr[i];
    bs[threadIdx.x] = bias[threadIdx.x];
    __syncthreads();

    int e = (blockIdx.x * blockDim.x + threadIdx.x) >> 5;
    int lane = threadIdx.x & 31;
    if (e >= N_EDGES) return;
    int s = src[e], d = dst[e];
    float at[8];
#pragma unroll
    for (int a = 0; a < 8; a++) at[a] = attr[(size_t)e * 8 + a];
    const __half* us = UV + (size_t)s * 512;
    const __half* vd = UV + (size_t)d * 512 + 256;
#pragma unroll
    for (int j = 0; j < 4; j++) {
        int c = j * 64 + lane * 2;
        float2 u = __half22float2(*(const __half2*)&us[c]);
        float2 v = __half22float2(*(const __half2*)&vd[c]);
        float a0 = u.x + v.x + bs[c];
        float a1 = u.y + v.y + bs[c + 1];
#pragma unroll
        for (int a = 0; a < 8; a++) {
            float2 w = *(const float2*)&Ws[a * 256 + c];
            a0 += at[a] * w.x;
            a1 += at[a] * w.y;
        }
        a0 = fmaxf(a0, 0.f);
        a1 = fmaxf(a1, 0.f);
        uint16_t h0, l0, h1, l1;
        fp16_split(a0, h0, l0);
        fp16_split(a1, h1, l1);
        size_t o = (size_t)e * H + c;
        *(uint32_t*)&outhi[o] = (uint32_t)h0 | ((uint32_t)h1 << 16);
        *(uint32_t*)&outlo[o] = (uint32_t)l0 | ((uint32_t)l1 << 16);
    }
}

// ---------------- host orchestration ------------------------------------------
#define SMEM_BF3 (NSTAGE * (2 * A_BYTES + 2 * B_BYTES))
#define SMEM_FP2 (NSTAGE * (2 * A_BYTES + 1 * B_BYTES))

static inline void run_gemm3(const uint16_t* Ahi, const uint16_t* Alo, int lda, int split,
                             const uint16_t* Bhi, const uint16_t* Blo, const float* bias,
                             float* Cf, uint16_t* Chi, uint16_t* Clo,
                             int M, int Nc, int K, int relu, int outMode)
{
    dim3 grid((Nc + 63) / 64, (M + 127) / 128);
    gemm_tc<0><<<grid, 256, SMEM_BF3>>>(Ahi, Alo, lda, split, Bhi, Blo, bias,
                                        Cf, Chi, Clo, nullptr, nullptr,
                                        M, Nc, K, relu, outMode);
}
static inline void run_gemm2(const uint16_t* Ahi, const uint16_t* Alo, int lda, int split,
                             const uint16_t* Bhi, const float* bias,
                             float* Cf, uint16_t* Chi, uint16_t* Clo,
                             int M, int Nc, int K, int relu, int outMode)
{
    dim3 grid((Nc + 63) / 64, (M + 127) / 128);
    gemm_tc<1><<<grid, 256, SMEM_FP2>>>(Ahi, Alo, lda, split, Bhi, nullptr, bias,
                                        Cf, Chi, Clo, nullptr, nullptr,
                                        M, Nc, K, relu, outMode);
}
static inline void run_gemm_final(const uint16_t* Ahi, const uint16_t* Alo, int lda,
                                  const uint16_t* Bhi, const float* bias,
                                  const float* W5, const float* b5, float* out,
                                  int M, int K)
{
    dim3 grid(1, (M + 127) / 128);
    gemm_tc<1><<<grid, 256, SMEM_FP2>>>(Ahi, Alo, lda, 0, Bhi, nullptr, bias,
                                        out, nullptr, nullptr, W5, b5,
                                        M, 64, K, 1, 2);
}

extern "C" void kernel_launch(void* const* d_in, const int* in_sizes, int n_in,
                              void* d_out, int out_size)
{
    (void)in_sizes; (void)n_in; (void)out_size;

    cudaFuncSetAttribute(gemm_tc<0>, cudaFuncAttributeMaxDynamicSharedMemorySize, SMEM_BF3);
    cudaFuncSetAttribute(gemm_tc<1>, cudaFuncAttributeMaxDynamicSharedMemorySize, SMEM_FP2);

    const float* x    = (const float*)d_in[0];
    const int*   ei   = (const int*)d_in[1];
    const float* attr = (const float*)d_in[2];
    const float* W[2][3]  = {{(const float*)d_in[3],  (const float*)d_in[5],  (const float*)d_in[7]},
                             {(const float*)d_in[9],  (const float*)d_in[11], (const float*)d_in[13]}};
    const float* bb[2][3] = {{(const float*)d_in[4],  (const float*)d_in[6],  (const float*)d_in[8]},
                             {(const float*)d_in[10], (const float*)d_in[12], (const float*)d_in[14]}};
    const float* gam[3] = {(const float*)d_in[15], (const float*)d_in[17], (const float*)d_in[19]};
    const float* bet[3] = {(const float*)d_in[16], (const float*)d_in[18], (const float*)d_in[20]};
    const float* Wc[5]  = {(const float*)d_in[21], (const float*)d_in[23], (const float*)d_in[25],
                           (const float*)d_in[27], (const float*)d_in[29]};
    const float* bc[5]  = {(const float*)d_in[22], (const float*)d_in[24], (const float*)d_in[26],
                           (const float*)d_in[28], (const float*)d_in[30]};

    const int* src = ei;
    const int* dst = ei + N_EDGES;
    float* out = (float*)d_out;

    float *isd, *big1, *big2, *csr_w, *bias512;
    uint16_t *a512hi, *a512lo, *acthi, *actlo, *xhi, *xlo, *e1hi, *e1lo, *e2hi, *e2lo, *whi, *wlo;
    int *rowstart, *cursor, *csr_src;
    cudaGetSymbolAddress((void**)&isd,  g_isd);
    cudaGetSymbolAddress((void**)&big1, g_big1);
    cudaGetSymbolAddress((void**)&big2, g_big2);
    cudaGetSymbolAddress((void**)&a512hi, g_a512hi);
    cudaGetSymbolAddress((void**)&a512lo, g_a512lo);
    cudaGetSymbolAddress((void**)&acthi, g_acthi);
    cudaGetSymbolAddress((void**)&actlo, g_actlo);
    cudaGetSymbolAddress((void**)&xhi, g_xhi);
    cudaGetSymbolAddress((void**)&xlo, g_xlo);
    cudaGetSymbolAddress((void**)&e1hi, g_e1hi);
    cudaGetSymbolAddress((void**)&e1lo, g_e1lo);
    cudaGetSymbolAddress((void**)&e2hi, g_e2hi);
    cudaGetSymbolAddress((void**)&e2lo, g_e2lo);
    cudaGetSymbolAddress((void**)&whi, g_whi);
    cudaGetSymbolAddress((void**)&wlo, g_wlo);
    cudaGetSymbolAddress((void**)&bias512, g_bias512);
    cudaGetSymbolAddress((void**)&rowstart, g_rowstart);
    cudaGetSymbolAddress((void**)&cursor,   g_cursor);
    cudaGetSymbolAddress((void**)&csr_src,  g_csr_src);
    cudaGetSymbolAddress((void**)&csr_w,    g_csr_w);
    uint16_t* big1h = (uint16_t*)big1;   // fp16 view of big1 (hw512 / UV)

    // degree + CSR first (layer-1 gather needs them)
    deg_init<<<(N_NODES + 255) / 256, 256>>>(isd, N_NODES);
    deg_count<<<(N_EDGES + 255) / 256, 256>>>(dst, isd, N_EDGES);
    deg_fin<<<(N_NODES + 255) / 256, 256>>>(isd, N_NODES);
    zero_int<<<(N_NODES + 255) / 256, 256>>>(cursor, N_NODES);
    count_int<<<(N_EDGES + 255) / 256, 256>>>(dst, cursor, N_EDGES);
    scan_deg<<<1, 1024>>>(cursor, rowstart);
    zero_int<<<(N_NODES + 255) / 256, 256>>>(cursor, N_NODES);
    csr_fill<<<(N_EDGES + 255) / 256, 256>>>(src, dst, rowstart, cursor, isd, csr_src, csr_w);

    // layer-1 reorder: xa = Â x (128-wide gather, bf16 split out)
    gcn_gather_x<<<(N_NODES * 32 + 255) / 256, 256>>>(x, rowstart, csr_src, csr_w, isd,
                                                      xhi, xlo);
    pack_bias512<<<2, 256>>>(bb[0][0], bb[1][0], bias512);
    pack2<<<(128 * 512 + 255) / 256, 256>>>(W[0][0], W[1][0], whi + OFF_WN1, wlo + OFF_WN1, 128 * 512);

    // agg512 = xa @ [W11|W21] + [b11|b21]  -> big2  [bf16x3, fp32 out]
    run_gemm3(xhi, xlo, D_IN, 0, whi + OFF_WN1, wlo + OFF_WN1, bias512,
              big2, nullptr, nullptr, N_NODES, 512, D_IN, 0, 0);

    // remaining weight packing (overlaps GEMM tail)
    pack2_fp16<<<(256 * 512 + 255) / 256, 256>>>(W[0][1], W[1][1], whi + OFF_WN2, 256 * 512);
    pack2_fp16<<<(256 * 512 + 255) / 256, 256>>>(W[0][2], W[1][2], whi + OFF_WN3, 256 * 512);
    pack_wuv_fp16<<<(256 * 512 + 255) / 256, 256>>>(Wc[0], whi + OFF_WUV);
    convert_fp16<<<(65536 + 255) / 256, 256>>>(Wc[1], whi + OFF_WC2, 65536);
    convert_fp16<<<(32768 + 255) / 256, 256>>>(Wc[2], whi + OFF_WC3, 32768);
    convert_fp16<<<(8192 + 255) / 256, 256>>>(Wc[3], whi + OFF_WC4, 8192);

    const int gather_blocks = (N_NODES * 32 + 255) / 256;
    const int NH512_2 = NH512 / 2;
    const int NH2 = NH / 2;

    // layer-1 BN (stats standalone; agg already in big2) -> fp16 split
    bn_zero512<<<1, 512>>>();
    bn_stats512<<<(N_NODES + 7) / 8, 256>>>(big2);
    bn_final512<<<1, 512>>>();
    bn_apply_split512<<<(NH512_2 + 255) / 256, 256>>>(big2, gam[0], bet[0],
                                                      a512hi, a512lo, NH512_2);

    // layers 2, 3: fp16x2 GEMM -> fp16 hw -> fp16-row gather (fused stats)
    const int woffN[2] = {OFF_WN2, OFF_WN3};
    for (int li = 1; li < 3; ++li) {
        run_gemm2(a512hi, a512lo, 512, 1, whi + woffN[li - 1], nullptr,
                  nullptr, big1h, nullptr, N_NODES, 512, H, 0, 3);
        bn_zero512<<<1, 512>>>();
        gcn_gather512h<<<gather_blocks, 256>>>((const __half*)big1h, rowstart, csr_src,
                                               csr_w, isd, bb[0][li], bb[1][li], big2);
        bn_final512<<<1, 512>>>();
        if (li < 2)
            bn_apply_split512<<<(NH512_2 + 255) / 256, 256>>>(big2, gam[li], bet[li],
                                                              a512hi, a512lo, NH512_2);
        else
            bn_add_convert<<<(NH2 + 255) / 256, 256>>>(big2, gam[li], bet[li],
                                                       acthi, actlo, NH2);
    }

    // U||V: [50k,256] @ [256,512] -> big1 (UV fp16)  [fp16x2]
    run_gemm2(acthi, actlo, H, 0, whi + OFF_WUV, nullptr,
              nullptr, big1h, nullptr, N_NODES, 512, H, 0, 3);
    edge_l1<<<(N_EDGES * 32 + 255) / 256, 256>>>((const __half*)big1h, attr,
                                                 Wc[0] + 512 * 256, bc[0],
                                                 src, dst, e1hi, e1lo);

    // edge MLP [fp16x2]
    run_gemm2(e1hi, e1lo, 256, 0, whi + OFF_WC2, bc[1],
              nullptr, e2hi, e2lo, N_EDGES, 256, 256, 1, 1);
    run_gemm2(e2hi, e2lo, 256, 0, whi + OFF_WC3, bc[2],
              nullptr, e1hi, e1lo, N_EDGES, 128, 256, 1, 1);
    // Wc4 + fused final 64->2 (out written directly)
    run_gemm_final(e1hi, e1lo, 128, whi + OFF_WC4, bc[3], Wc[4], bc[4], out,
                   N_EDGES, 128);
}

// round 17
// speedup vs baseline: 1.0912x; 1.0912x over previous
#include <cuda_runtime.h>
#include <cuda_bf16.h>
#include <cuda_fp16.h>
#include <cstdint>
#include <cstddef>

#define N_NODES 50000
#define N_EDGES 400000
#define H 256
#define D_IN 128
#define NH (N_NODES * H)
#define NH512 (N_NODES * 512)

// ---------------- scratch (static device globals; no allocations) ------------
__device__ float g_isd[N_NODES];
__device__ float g_big1[NH512];                  // hw512 fp32 / UV fp16 storage
__device__ float g_big2[NH512];                  // agg512 fp32
__device__ __align__(16) uint16_t g_a512hi[NH512];   // fp16 bits
__device__ __align__(16) uint16_t g_a512lo[NH512];
__device__ __align__(16) uint16_t g_acthi[NH];   // hc fp16 hi
__device__ __align__(16) uint16_t g_actlo[NH];
__device__ __align__(16) uint16_t g_xhi[N_NODES * D_IN];   // (Â x) bf16 hi
__device__ __align__(16) uint16_t g_xlo[N_NODES * D_IN];
__device__ __align__(16) uint16_t g_e1hi[(size_t)N_EDGES * H];   // fp16 bits
__device__ __align__(16) uint16_t g_e1lo[(size_t)N_EDGES * H];
__device__ __align__(16) uint16_t g_e2hi[(size_t)N_EDGES * H];
__device__ __align__(16) uint16_t g_e2lo[(size_t)N_EDGES * H];
// weight pool (element offsets), B stored [K, N] row-major
#define OFF_WN1 0        // [128,512] bf16 hi/lo
#define OFF_WN2 65536    // [256,512] fp16 single
#define OFF_WN3 196608   // [256,512] fp16 single
#define OFF_WUV 327680   // [256,512] fp16 single
#define OFF_WC2 458752   // [256,256] fp16 single
#define OFF_WC3 524288   // [256,128] fp16 single
#define OFF_WC4 557056   // [128,64]  fp16 single
#define W_TOTAL 565248
__device__ __align__(16) uint16_t g_whi[W_TOTAL];
__device__ __align__(16) uint16_t g_wlo[W_TOTAL];
__device__ float g_sum[512];
__device__ float g_sq[512];
__device__ float g_mean[512];
__device__ float g_rstd[512];
__device__ float g_bias512[512];
// CSR
__device__ int g_rowstart[N_NODES + 1];
__device__ int g_cursor[N_NODES];
__device__ int g_csr_src[N_EDGES];
__device__ float g_csr_w[N_EDGES];

// ---------------- helpers -----------------------------------------------------
__device__ __forceinline__ void bf16_split(float v, uint16_t& hi, uint16_t& lo) {
    __nv_bfloat16 h = __float2bfloat16_rn(v);
    float r = v - __bfloat162float(h);
    __nv_bfloat16 l = __float2bfloat16_rn(r);
    hi = *reinterpret_cast<uint16_t*>(&h);
    lo = *reinterpret_cast<uint16_t*>(&l);
}
__device__ __forceinline__ void fp16_split(float v, uint16_t& hi, uint16_t& lo) {
    __half h = __float2half_rn(v);
    float r = v - __half2float(h);
    __half l = __float2half_rn(r);
    hi = *reinterpret_cast<uint16_t*>(&h);
    lo = *reinterpret_cast<uint16_t*>(&l);
}
__device__ __forceinline__ uint32_t smem_u32(const void* p) {
    uint32_t a;
    asm("{ .reg .u64 t; cvta.to.shared.u64 t, %1; cvt.u32.u64 %0, t; }" : "=r"(a) : "l"(p));
    return a;
}
__device__ __forceinline__ void cpasync16(uint32_t dst, const void* src, bool ok) {
    int sz = ok ? 16 : 0;
    asm volatile("cp.async.cg.shared.global [%0], [%1], 16, %2;"
                 :: "r"(dst), "l"(src), "r"(sz));
}
__device__ __forceinline__ void cpasync_commit() {
    asm volatile("cp.async.commit_group;" ::: "memory");
}
__device__ __forceinline__ void cpasync_wait0() { asm volatile("cp.async.wait_group 0;" ::: "memory"); }
__device__ __forceinline__ void cpasync_wait1() { asm volatile("cp.async.wait_group 1;" ::: "memory"); }

// ---------------- degree / CSR -------------------------------------------------
__global__ void deg_init(float* d, int n) {
    int i = blockIdx.x * blockDim.x + threadIdx.x;
    if (i < n) d[i] = 1.0f;
}
__global__ void deg_count(const int* __restrict__ dst, float* d, int e) {
    int i = blockIdx.x * blockDim.x + threadIdx.x;
    if (i < e) atomicAdd(&d[dst[i]], 1.0f);
}
__global__ void deg_fin(float* d, int n) {
    int i = blockIdx.x * blockDim.x + threadIdx.x;
    if (i < n) d[i] = rsqrtf(d[i]);
}
__global__ void zero_int(int* p, int n) {
    int i = blockIdx.x * blockDim.x + threadIdx.x;
    if (i < n) p[i] = 0;
}
__global__ void count_int(const int* __restrict__ dst, int* cnt, int e) {
    int i = blockIdx.x * blockDim.x + threadIdx.x;
    if (i < e) atomicAdd(&cnt[dst[i]], 1);
}
__global__ void scan_deg(const int* __restrict__ cnt, int* __restrict__ rowstart) {
    __shared__ int ssum[1024];
    const int CHUNK = (N_NODES + 1023) / 1024;
    int t = threadIdx.x;
    int c0 = t * CHUNK;
    int s = 0;
    for (int i = 0; i < CHUNK; i++) {
        int idx = c0 + i;
        if (idx < N_NODES) s += cnt[idx];
    }
    ssum[t] = s;
    __syncthreads();
    for (int off = 1; off < 1024; off <<= 1) {
        int v = (t >= off) ? ssum[t - off] : 0;
        __syncthreads();
        ssum[t] += v;
        __syncthreads();
    }
    int run = (t > 0) ? ssum[t - 1] : 0;
    for (int i = 0; i < CHUNK; i++) {
        int idx = c0 + i;
        if (idx < N_NODES) {
            rowstart[idx] = run;
            run += cnt[idx];
        }
    }
    if (t == 1023) rowstart[N_NODES] = run;
}
__global__ void csr_fill(const int* __restrict__ src, const int* __restrict__ dst,
                         const int* __restrict__ rowstart, int* cursor,
                         const float* __restrict__ isd, int* __restrict__ csr_src,
                         float* __restrict__ csr_w)
{
    int e = blockIdx.x * blockDim.x + threadIdx.x;
    if (e < N_EDGES) {
        int d = dst[e], s = src[e];
        int pos = rowstart[d] + atomicAdd(&cursor[d], 1);
        csr_src[pos] = s;
        csr_w[pos] = isd[s] * isd[d];
    }
}

// ---------------- conversion / packing ----------------------------------------
__global__ void convert_fp16(const float* __restrict__ in, uint16_t* __restrict__ hi, int n)
{
    int i = blockIdx.x * blockDim.x + threadIdx.x;
    if (i < n) {
        __half h = __float2half_rn(in[i]);
        hi[i] = *reinterpret_cast<uint16_t*>(&h);
    }
}
// pack two [K,256] weights side by side -> [K,512] (bf16 split)
__global__ void pack2(const float* __restrict__ Wa, const float* __restrict__ Wb,
                      uint16_t* __restrict__ hi, uint16_t* __restrict__ lo, int total)
{
    int idx = blockIdx.x * blockDim.x + threadIdx.x;
    if (idx < total) {
        int k = idx >> 9, n = idx & 511;
        float v = (n < 256) ? Wa[k * 256 + n] : Wb[k * 256 + (n - 256)];
        uint16_t h, l;
        bf16_split(v, h, l);
        hi[idx] = h;
        lo[idx] = l;
    }
}
// pack two [K,256] weights side by side -> [K,512] fp16 single
__global__ void pack2_fp16(const float* __restrict__ Wa, const float* __restrict__ Wb,
                           uint16_t* __restrict__ hi, int total)
{
    int idx = blockIdx.x * blockDim.x + threadIdx.x;
    if (idx < total) {
        int k = idx >> 9, n = idx & 511;
        float v = (n < 256) ? Wa[k * 256 + n] : Wb[k * 256 + (n - 256)];
        __half h = __float2half_rn(v);
        hi[idx] = *reinterpret_cast<uint16_t*>(&h);
    }
}
// pack [Wc1a | Wc1b] (stacked in K) -> [256, 512] fp16 single
__global__ void pack_wuv_fp16(const float* __restrict__ Wc1, uint16_t* __restrict__ hi)
{
    int idx = blockIdx.x * blockDim.x + threadIdx.x;
    if (idx < 256 * 512) {
        int k = idx >> 9, n = idx & 511;
        float v = (n < 256) ? Wc1[k * 256 + n] : Wc1[(256 + k) * 256 + (n - 256)];
        __half h = __float2half_rn(v);
        hi[idx] = *reinterpret_cast<uint16_t*>(&h);
    }
}
__global__ void pack_bias512(const float* __restrict__ b1, const float* __restrict__ b2,
                             float* __restrict__ out)
{
    int i = blockIdx.x * 256 + threadIdx.x;
    if (i < 512) out[i] = (i < 256) ? b1[i] : b2[i - 256];
}

// ---------------- tensor-core GEMM (cp.async, CTA 128x64, occ 3) --------------
// FP16MODE=0: bf16x3 (A hi/lo, B hi/lo). FP16MODE=1: fp16x2 (A hi/lo, B single).
// outMode: 0 fp32 C; 1 split hi/lo C; 2 fused final 64->2; 3 fp16-single C.
#define AS_STRIDE 40
#define BS_STR 72
#define A_BYTES (128 * AS_STRIDE * 2)     // 10240
#define B_BYTES (32 * BS_STR * 2)         // 4608
#define NSTAGE 2

__device__ __forceinline__ void ldmA(uint32_t r[4], uint32_t base, int row0, int ks, int lane) {
    int mat = lane >> 3, rr = lane & 7;
    int row = row0 + (mat & 1) * 8 + rr;
    int k = ks + (mat >> 1) * 8;
    uint32_t addr = base + (uint32_t)(row * AS_STRIDE + k) * 2u;
    asm volatile("ldmatrix.sync.aligned.m8n8.x4.shared.b16 {%0,%1,%2,%3}, [%4];"
                 : "=r"(r[0]), "=r"(r[1]), "=r"(r[2]), "=r"(r[3]) : "r"(addr));
}
__device__ __forceinline__ void ldmB(uint32_t r[4], uint32_t base, int ks, int n0, int lane) {
    int part = lane >> 3, rr = lane & 7;
    int k = ks + (part & 1) * 8 + rr;
    int n = n0 + (part >> 1) * 8;
    uint32_t addr = base + (uint32_t)(k * BS_STR + n) * 2u;
    asm volatile("ldmatrix.sync.aligned.m8n8.x4.trans.shared.b16 {%0,%1,%2,%3}, [%4];"
                 : "=r"(r[0]), "=r"(r[1]), "=r"(r[2]), "=r"(r[3]) : "r"(addr));
}
__device__ __forceinline__ void mma_bf16(float d[4], const uint32_t a[4], const uint32_t b[2]) {
    asm volatile("mma.sync.aligned.m16n8k16.row.col.f32.bf16.bf16.f32 "
                 "{%0,%1,%2,%3},{%4,%5,%6,%7},{%8,%9},{%0,%1,%2,%3};"
                 : "+f"(d[0]), "+f"(d[1]), "+f"(d[2]), "+f"(d[3])
                 : "r"(a[0]), "r"(a[1]), "r"(a[2]), "r"(a[3]), "r"(b[0]), "r"(b[1]));
}
__device__ __forceinline__ void mma_fp16(float d[4], const uint32_t a[4], const uint32_t b[2]) {
    asm volatile("mma.sync.aligned.m16n8k16.row.col.f32.f16.f16.f32 "
                 "{%0,%1,%2,%3},{%4,%5,%6,%7},{%8,%9},{%0,%1,%2,%3};"
                 : "+f"(d[0]), "+f"(d[1]), "+f"(d[2]), "+f"(d[3])
                 : "r"(a[0]), "r"(a[1]), "r"(a[2]), "r"(a[3]), "r"(b[0]), "r"(b[1]));
}

template <int FP16MODE>
__global__ __launch_bounds__(256, 3)
void gemm_tc(const uint16_t* __restrict__ Ahi, const uint16_t* __restrict__ Alo,
             int lda, int splitHalf,
             const uint16_t* __restrict__ Bhi, const uint16_t* __restrict__ Blo,
             const float* __restrict__ bias, float* __restrict__ Cf,
             uint16_t* __restrict__ Chi, uint16_t* __restrict__ Clo,
             const float* __restrict__ W5, const float* __restrict__ b5,
             int M, int Nc, int K, int doRelu, int outMode)
{
    constexpr int STAGE_BYTES = 2 * A_BYTES + (FP16MODE ? 1 : 2) * B_BYTES;
    extern __shared__ __align__(16) uint8_t dynsmem[];
    uint32_t sbase = smem_u32(dynsmem);
    __shared__ float s_w5[128];
    __shared__ float s_part[4][32][2];

    int tid = threadIdx.x;
    int lane = tid & 31;
    int wid = tid >> 5;
    int wm = (wid & 3) * 32;
    int wn = (wid >> 2) * 32;
    int m0 = blockIdx.y * 128;
    int n0 = blockIdx.x * 64;
    int koff = (splitHalf && n0 >= 256) ? 256 : 0;

    if (outMode == 2 && tid < 128) s_w5[tid] = W5[tid];

    float d[2][4][4];
#pragma unroll
    for (int mt = 0; mt < 2; mt++)
#pragma unroll
        for (int nt = 0; nt < 4; nt++)
#pragma unroll
            for (int q = 0; q < 4; q++) d[mt][nt][q] = 0.f;

    int KT = K / 32;

    auto load_stage = [&](int s, int kc) {
        uint32_t base = sbase + (uint32_t)s * STAGE_BYTES;
#pragma unroll
        for (int q = 0; q < 2; q++) {
            int ch = tid + q * 256;
            int row = ch >> 2, c16 = ch & 3;
            bool ok = (m0 + row) < M;
            size_t go = (size_t)(m0 + (ok ? row : 0)) * lda + koff + kc + c16 * 8;
            uint32_t dA = base + (uint32_t)(row * (AS_STRIDE * 2) + c16 * 16);
            cpasync16(dA, Ahi + go, ok);
            cpasync16(dA + A_BYTES, Alo + go, ok);
        }
        {
            int kr = tid >> 3, nn = (tid & 7) * 8;
            bool ok = (n0 + nn) < Nc;
            size_t go = (size_t)(kc + kr) * Nc + (ok ? (n0 + nn) : 0);
            uint32_t dB = base + 2 * A_BYTES + (uint32_t)(kr * (BS_STR * 2) + nn * 2);
            cpasync16(dB, Bhi + go, ok);
            if (!FP16MODE) cpasync16(dB + B_BYTES, Blo + go, ok);
        }
        cpasync_commit();
    };

    load_stage(0, 0);
    load_stage(1, 32);   // KT >= 4 for all our GEMMs

    for (int kt = 0; kt < KT; kt++) {
        int s = kt & 1;
        if (kt + 1 < KT) cpasync_wait1(); else cpasync_wait0();
        __syncthreads();

        uint32_t stg = sbase + (uint32_t)s * STAGE_BYTES;
        uint32_t sAhi = stg;
        uint32_t sAlo = stg + A_BYTES;
        uint32_t sBhi = stg + 2 * A_BYTES;
        uint32_t sBlo = stg + 2 * A_BYTES + B_BYTES;   // unused in fp16 mode

#pragma unroll
        for (int ks = 0; ks < 32; ks += 16) {
            uint32_t AH[2][4], AL[2][4];
#pragma unroll
            for (int mt = 0; mt < 2; mt++) {
                ldmA(AH[mt], sAhi, wm + mt * 16, ks, lane);
                ldmA(AL[mt], sAlo, wm + mt * 16, ks, lane);
            }
#pragma unroll
            for (int jp = 0; jp < 2; jp++) {
                uint32_t bh[4];
                ldmB(bh, sBhi, ks, wn + jp * 16, lane);
                if (FP16MODE) {
#pragma unroll
                    for (int mt = 0; mt < 2; mt++) {
                        mma_fp16(d[mt][2 * jp], AH[mt], bh);
                        mma_fp16(d[mt][2 * jp + 1], AH[mt], bh + 2);
                        mma_fp16(d[mt][2 * jp], AL[mt], bh);
                        mma_fp16(d[mt][2 * jp + 1], AL[mt], bh + 2);
                    }
                } else {
                    uint32_t bl[4];
                    ldmB(bl, sBlo, ks, wn + jp * 16, lane);
#pragma unroll
                    for (int mt = 0; mt < 2; mt++) {
                        mma_bf16(d[mt][2 * jp], AH[mt], bh);
                        mma_bf16(d[mt][2 * jp + 1], AH[mt], bh + 2);
                        mma_bf16(d[mt][2 * jp], AL[mt], bh);
                        mma_bf16(d[mt][2 * jp + 1], AL[mt], bh + 2);
                        mma_bf16(d[mt][2 * jp], AH[mt], bl);
                        mma_bf16(d[mt][2 * jp + 1], AH[mt], bl + 2);
                    }
                }
            }
        }

        if (kt + 2 < KT) {
            __syncthreads();            // all warps done reading stage s
            load_stage(s, (kt + 2) * 32);
        }
    }

    int g = lane >> 2, tg = lane & 3;

    if (outMode == 2) {
        // fused final: relu(v)+bias (bc4) then dot with W5[64,2]; M % 128 == 0.
        float p[2][2][2];
#pragma unroll
        for (int mt = 0; mt < 2; mt++)
#pragma unroll
            for (int hh = 0; hh < 2; hh++) { p[mt][hh][0] = 0.f; p[mt][hh][1] = 0.f; }
#pragma unroll
        for (int mt = 0; mt < 2; mt++)
#pragma unroll
            for (int hh = 0; hh < 2; hh++)
#pragma unroll
                for (int nt = 0; nt < 4; nt++) {
                    int col = wn + nt * 8 + tg * 2;
                    float v0 = fmaxf(d[mt][nt][hh * 2 + 0] + bias[col], 0.f);
                    float v1 = fmaxf(d[mt][nt][hh * 2 + 1] + bias[col + 1], 0.f);
                    p[mt][hh][0] += v0 * s_w5[col * 2] + v1 * s_w5[(col + 1) * 2];
                    p[mt][hh][1] += v0 * s_w5[col * 2 + 1] + v1 * s_w5[(col + 1) * 2 + 1];
                }
#pragma unroll
        for (int mt = 0; mt < 2; mt++)
#pragma unroll
            for (int hh = 0; hh < 2; hh++)
#pragma unroll
                for (int o = 0; o < 2; o++) {
                    float v = p[mt][hh][o];
                    v += __shfl_xor_sync(0xffffffffu, v, 1);
                    v += __shfl_xor_sync(0xffffffffu, v, 2);
                    p[mt][hh][o] = v;
                }
        int wmb = wid & 3;
        if ((wid >> 2) == 1 && tg == 0) {
#pragma unroll
            for (int mt = 0; mt < 2; mt++)
#pragma unroll
                for (int hh = 0; hh < 2; hh++) {
                    int rib = mt * 16 + hh * 8 + g;
                    s_part[wmb][rib][0] = p[mt][hh][0];
                    s_part[wmb][rib][1] = p[mt][hh][1];
                }
        }
        __syncthreads();
        if ((wid >> 2) == 0 && tg == 0) {
            float bb0 = b5[0], bb1 = b5[1];
#pragma unroll
            for (int mt = 0; mt < 2; mt++)
#pragma unroll
                for (int hh = 0; hh < 2; hh++) {
                    int rib = mt * 16 + hh * 8 + g;
                    int row = m0 + wm + rib;
                    float a0 = p[mt][hh][0] + s_part[wmb][rib][0] + bb0;
                    float a1 = p[mt][hh][1] + s_part[wmb][rib][1] + bb1;
                    *(float2*)&Cf[(size_t)row * 2] = make_float2(a0, a1);
                }
        }
        return;
    }

#pragma unroll
    for (int mt = 0; mt < 2; mt++) {
#pragma unroll
        for (int hh = 0; hh < 2; hh++) {
            int row = m0 + wm + mt * 16 + g + hh * 8;
            if (row >= M) continue;
#pragma unroll
            for (int nt = 0; nt < 4; nt++) {
                int col = n0 + wn + nt * 8 + tg * 2;
                if (col >= Nc) continue;
                float v0 = d[mt][nt][hh * 2 + 0];
                float v1 = d[mt][nt][hh * 2 + 1];
                if (bias) { v0 += bias[col]; v1 += bias[col + 1]; }
                if (doRelu) { v0 = fmaxf(v0, 0.f); v1 = fmaxf(v1, 0.f); }
                size_t o = (size_t)row * Nc + col;
                if (outMode == 0) {
                    *(float2*)&Cf[o] = make_float2(v0, v1);
                } else if (outMode == 3) {
                    __half h0 = __float2half_rn(v0);
                    __half h1 = __float2half_rn(v1);
                    *(uint32_t*)&Chi[o] = (uint32_t)*(uint16_t*)&h0 |
                                          ((uint32_t)*(uint16_t*)&h1 << 16);
                } else {
                    uint16_t h0, l0, h1, l1;
                    if (FP16MODE) { fp16_split(v0, h0, l0); fp16_split(v1, h1, l1); }
                    else          { bf16_split(v0, h0, l0); bf16_split(v1, h1, l1); }
                    *(uint32_t*)&Chi[o] = (uint32_t)h0 | ((uint32_t)h1 << 16);
                    *(uint32_t*)&Clo[o] = (uint32_t)l0 | ((uint32_t)l1 << 16);
                }
            }
        }
    }
}

// ---------------- layer-1: 128-wide CSR gather of x -> bf16 split -------------
__global__ __launch_bounds__(256)
void gcn_gather_x(const float* __restrict__ x, const int* __restrict__ rowstart,
                  const int* __restrict__ csr_src, const float* __restrict__ csr_w,
                  const float* __restrict__ isd, uint16_t* __restrict__ outhi,
                  uint16_t* __restrict__ outlo)
{
    int w = (blockIdx.x * 256 + threadIdx.x) >> 5;
    int lane = threadIdx.x & 31;
    if (w >= N_NODES) return;
    float s = isd[w];
    float s2 = s * s;
    float4 v = *(const float4*)(x + (size_t)w * D_IN + lane * 4);
    float acc[4] = {v.x * s2, v.y * s2, v.z * s2, v.w * s2};
    int st = rowstart[w], en = rowstart[w + 1];
    for (int base = st; base < en; base += 32) {
        int n = en - base;
        if (n > 32) n = 32;
        int mys = (lane < n) ? csr_src[base + lane] : 0;
        float myw = (lane < n) ? csr_w[base + lane] : 0.f;
        for (int t = 0; t < n; t++) {
            int sidx = __shfl_sync(0xffffffffu, mys, t);
            float wt = __shfl_sync(0xffffffffu, myw, t);
            float4 hv = *(const float4*)(x + (size_t)sidx * D_IN + lane * 4);
            acc[0] += hv.x * wt;
            acc[1] += hv.y * wt;
            acc[2] += hv.z * wt;
            acc[3] += hv.w * wt;
        }
    }
    uint16_t h[4], l[4];
#pragma unroll
    for (int j = 0; j < 4; j++) bf16_split(acc[j], h[j], l[j]);
    size_t o = (size_t)w * D_IN + lane * 4;
    *(uint2*)&outhi[o] = make_uint2((uint32_t)h[0] | ((uint32_t)h[1] << 16),
                                    (uint32_t)h[2] | ((uint32_t)h[3] << 16));
    *(uint2*)&outlo[o] = make_uint2((uint32_t)l[0] | ((uint32_t)l[1] << 16),
                                    (uint32_t)l[2] | ((uint32_t)l[3] << 16));
}

// standalone BN stats over a [N,512] fp32 buffer
__global__ void bn_stats512(const float* __restrict__ h)
{
    int tid = threadIdx.x;
    int node0 = blockIdx.x * 8;
    float s0 = 0.f, q0 = 0.f, s1 = 0.f, q1 = 0.f;
#pragma unroll
    for (int r = 0; r < 8; r++) {
        int node = node0 + r;
        if (node < N_NODES) {
            float v0 = h[(size_t)node * 512 + tid];
            float v1 = h[(size_t)node * 512 + tid + 256];
            s0 += v0; q0 += v0 * v0;
            s1 += v1; q1 += v1 * v1;
        }
    }
    atomicAdd(&g_sum[tid], s0);
    atomicAdd(&g_sq[tid], q0);
    atomicAdd(&g_sum[tid + 256], s1);
    atomicAdd(&g_sq[tid + 256], q1);
}

// ---------------- GCN aggregation: 512-wide CSR gather (float4) + BN stats ----
__global__ __launch_bounds__(256)
void gcn_gather512(const float* __restrict__ hw, const int* __restrict__ rowstart,
                   const int* __restrict__ csr_src, const float* __restrict__ csr_w,
                   const float* __restrict__ isd, const float* __restrict__ b1,
                   const float* __restrict__ b2, float* __restrict__ agg)
{
    int tid = threadIdx.x;
    int w = (blockIdx.x * 256 + tid) >> 5;
    int lane = tid & 31;
    if (w < N_NODES) {
        float s = isd[w];
        float s2 = s * s;
        const float* hrow = hw + (size_t)w * 512;
        float4 acc[4];
#pragma unroll
        for (int j = 0; j < 4; j++) {
            int c = lane * 4 + j * 128;
            float4 hv = *(const float4*)&hrow[c];
            const float* bp = (j < 2) ? &b1[c] : &b2[c - 256];
            float4 bv = *(const float4*)bp;
            acc[j] = make_float4(hv.x * s2 + bv.x, hv.y * s2 + bv.y,
                                 hv.z * s2 + bv.z, hv.w * s2 + bv.w);
        }
        int st = rowstart[w], en = rowstart[w + 1];
        for (int base = st; base < en; base += 32) {
            int n = en - base;
            if (n > 32) n = 32;
            int mys = (lane < n) ? csr_src[base + lane] : 0;
            float myw = (lane < n) ? csr_w[base + lane] : 0.f;
            for (int t = 0; t < n; t++) {
                int sidx = __shfl_sync(0xffffffffu, mys, t);
                float wt = __shfl_sync(0xffffffffu, myw, t);
                const float* hs = hw + (size_t)sidx * 512;
#pragma unroll
                for (int j = 0; j < 4; j++) {
                    float4 hv = *(const float4*)&hs[lane * 4 + j * 128];
                    acc[j].x += hv.x * wt;
                    acc[j].y += hv.y * wt;
                    acc[j].z += hv.z * wt;
                    acc[j].w += hv.w * wt;
                }
            }
        }
        float* arow = agg + (size_t)w * 512;
#pragma unroll
        for (int j = 0; j < 4; j++)
            *(float4*)&arow[lane * 4 + j * 128] = acc[j];
    }
    __syncthreads();
    int node0 = (blockIdx.x * 256) >> 5;
    float s0 = 0.f, q0 = 0.f, s1 = 0.f, q1 = 0.f;
#pragma unroll
    for (int r = 0; r < 8; r++) {
        int node = node0 + r;
        if (node < N_NODES) {
            float v0 = agg[(size_t)node * 512 + tid];
            float v1 = agg[(size_t)node * 512 + tid + 256];
            s0 += v0; q0 += v0 * v0;
            s1 += v1; q1 += v1 * v1;
        }
    }
    atomicAdd(&g_sum[tid], s0);
    atomicAdd(&g_sq[tid], q0);
    atomicAdd(&g_sum[tid + 256], s1);
    atomicAdd(&g_sq[tid + 256], q1);
}

// ---------------- BatchNorm ----------------------------------------------------
__global__ void bn_zero512() {
    int c = threadIdx.x;
    g_sum[c] = 0.0f;
    g_sq[c] = 0.0f;
}
__global__ void bn_final512() {
    int c = threadIdx.x;
    float m = g_sum[c] * (1.0f / N_NODES);
    float v = g_sq[c] * (1.0f / N_NODES) - m * m;
    g_mean[c] = m;
    g_rstd[c] = rsqrtf(v + 1e-5f);
}
// BN + ReLU -> fp16 hi/lo split (feeds fp16x2 node GEMMs)
__global__ void bn_apply_split512(const float* __restrict__ h, const float* __restrict__ g,
                                  const float* __restrict__ be, uint16_t* __restrict__ hi,
                                  uint16_t* __restrict__ lo, int n2)
{
    int i2 = blockIdx.x * blockDim.x + threadIdx.x;
    if (i2 < n2) {
        int i = i2 * 2;
        int c0 = i & 511, c1 = c0 + 1;
        float v0 = fmaxf(g[c0 & 255] * (h[i] - g_mean[c0]) * g_rstd[c0] + be[c0 & 255], 0.f);
        float v1 = fmaxf(g[c1 & 255] * (h[i + 1] - g_mean[c1]) * g_rstd[c1] + be[c1 & 255], 0.f);
        uint16_t h0, l0, h1, l1;
        fp16_split(v0, h0, l0);
        fp16_split(v1, h1, l1);
        *(uint32_t*)&hi[i] = (uint32_t)h0 | ((uint32_t)h1 << 16);
        *(uint32_t*)&lo[i] = (uint32_t)l0 | ((uint32_t)l1 << 16);
    }
}
// layer3: BN both halves + add -> hc fp16 hi/lo (feeds fp16x2 UV GEMM)
__global__ void bn_add_convert(const float* __restrict__ h, const float* __restrict__ g,
                               const float* __restrict__ be, uint16_t* __restrict__ hi,
                               uint16_t* __restrict__ lo, int n2)
{
    int i2 = blockIdx.x * blockDim.x + threadIdx.x;
    if (i2 < n2) {
        int i = i2 * 2;
        int r = i >> 8;
        int c0 = i & 255, c1 = c0 + 1;
        const float* row = h + (size_t)r * 512;
        float L0 = fmaxf(g[c0] * (row[c0] - g_mean[c0]) * g_rstd[c0] + be[c0], 0.f);
        float R0 = fmaxf(g[c0] * (row[c0 + 256] - g_mean[c0 + 256]) * g_rstd[c0 + 256] + be[c0], 0.f);
        float L1 = fmaxf(g[c1] * (row[c1] - g_mean[c1]) * g_rstd[c1] + be[c1], 0.f);
        float R1 = fmaxf(g[c1] * (row[c1 + 256] - g_mean[c1 + 256]) * g_rstd[c1 + 256] + be[c1], 0.f);
        float v0 = L0 + R0;
        float v1 = L1 + R1;
        uint16_t h0, l0, h1, l1;
        fp16_split(v0, h0, l0);
        fp16_split(v1, h1, l1);
        *(uint32_t*)&hi[i] = (uint32_t)h0 | ((uint32_t)h1 << 16);
        *(uint32_t*)&lo[i] = (uint32_t)l0 | ((uint32_t)l1 << 16);
    }
}

// ---------------- fused edge-MLP layer 1 (fp16 UV in, fp16 hi/lo out) ---------
__global__ __launch_bounds__(256)
void edge_l1(const __half* __restrict__ UV, const float* __restrict__ attr,
             const float* __restrict__ Wattr, const float* __restrict__ bias,
             const int* __restrict__ src, const int* __restrict__ dst,
             uint16_t* __restrict__ outhi, uint16_t* __restrict__ outlo)
{
    __shared__ float Ws[8 * 256];
    __shared__ float bs[256];
    for (int i = threadIdx.x; i < 8 * 256; i += 256) Ws[i] = Wattr[i];
    bs[threadIdx.x] = bias[threadIdx.x];
    __syncthreads();

    int e = (blockIdx.x * blockDim.x + threadIdx.x) >> 5;
    int lane = threadIdx.x & 31;
    if (e >= N_EDGES) return;
    int s = src[e], d = dst[e];
    float at[8];
#pragma unroll
    for (int a = 0; a < 8; a++) at[a] = attr[(size_t)e * 8 + a];
    const __half* us = UV + (size_t)s * 512;
    const __half* vd = UV + (size_t)d * 512 + 256;
#pragma unroll
    for (int j = 0; j < 4; j++) {
        int c = j * 64 + lane * 2;
        float2 u = __half22float2(*(const __half2*)&us[c]);
        float2 v = __half22float2(*(const __half2*)&vd[c]);
        float a0 = u.x + v.x + bs[c];
        float a1 = u.y + v.y + bs[c + 1];
#pragma unroll
        for (int a = 0; a < 8; a++) {
            float2 w = *(const float2*)&Ws[a * 256 + c];
            a0 += at[a] * w.x;
            a1 += at[a] * w.y;
        }
        a0 = fmaxf(a0, 0.f);
        a1 = fmaxf(a1, 0.f);
        uint16_t h0, l0, h1, l1;
        fp16_split(a0, h0, l0);
        fp16_split(a1, h1, l1);
        size_t o = (size_t)e * H + c;
        *(uint32_t*)&outhi[o] = (uint32_t)h0 | ((uint32_t)h1 << 16);
        *(uint32_t*)&outlo[o] = (uint32_t)l0 | ((uint32_t)l1 << 16);
    }
}

// ---------------- host orchestration ------------------------------------------
#define SMEM_BF3 (NSTAGE * (2 * A_BYTES + 2 * B_BYTES))
#define SMEM_FP2 (NSTAGE * (2 * A_BYTES + 1 * B_BYTES))

static inline void run_gemm3(const uint16_t* Ahi, const uint16_t* Alo, int lda, int split,
                             const uint16_t* Bhi, const uint16_t* Blo, const float* bias,
                             float* Cf, uint16_t* Chi, uint16_t* Clo,
                             int M, int Nc, int K, int relu, int outMode)
{
    dim3 grid((Nc + 63) / 64, (M + 127) / 128);
    gemm_tc<0><<<grid, 256, SMEM_BF3>>>(Ahi, Alo, lda, split, Bhi, Blo, bias,
                                        Cf, Chi, Clo, nullptr, nullptr,
                                        M, Nc, K, relu, outMode);
}
static inline void run_gemm2(const uint16_t* Ahi, const uint16_t* Alo, int lda, int split,
                             const uint16_t* Bhi, const float* bias,
                             float* Cf, uint16_t* Chi, uint16_t* Clo,
                             int M, int Nc, int K, int relu, int outMode)
{
    dim3 grid((Nc + 63) / 64, (M + 127) / 128);
    gemm_tc<1><<<grid, 256, SMEM_FP2>>>(Ahi, Alo, lda, split, Bhi, nullptr, bias,
                                        Cf, Chi, Clo, nullptr, nullptr,
                                        M, Nc, K, relu, outMode);
}
static inline void run_gemm_final(const uint16_t* Ahi, const uint16_t* Alo, int lda,
                                  const uint16_t* Bhi, const float* bias,
                                  const float* W5, const float* b5, float* out,
                                  int M, int K)
{
    dim3 grid(1, (M + 127) / 128);
    gemm_tc<1><<<grid, 256, SMEM_FP2>>>(Ahi, Alo, lda, 0, Bhi, nullptr, bias,
                                        out, nullptr, nullptr, W5, b5,
                                        M, 64, K, 1, 2);
}

extern "C" void kernel_launch(void* const* d_in, const int* in_sizes, int n_in,
                              void* d_out, int out_size)
{
    (void)in_sizes; (void)n_in; (void)out_size;

    cudaFuncSetAttribute(gemm_tc<0>, cudaFuncAttributeMaxDynamicSharedMemorySize, SMEM_BF3);
    cudaFuncSetAttribute(gemm_tc<1>, cudaFuncAttributeMaxDynamicSharedMemorySize, SMEM_FP2);

    const float* x    = (const float*)d_in[0];
    const int*   ei   = (const int*)d_in[1];
    const float* attr = (const float*)d_in[2];
    const float* W[2][3]  = {{(const float*)d_in[3],  (const float*)d_in[5],  (const float*)d_in[7]},
                             {(const float*)d_in[9],  (const float*)d_in[11], (const float*)d_in[13]}};
    const float* bb[2][3] = {{(const float*)d_in[4],  (const float*)d_in[6],  (const float*)d_in[8]},
                             {(const float*)d_in[10], (const float*)d_in[12], (const float*)d_in[14]}};
    const float* gam[3] = {(const float*)d_in[15], (const float*)d_in[17], (const float*)d_in[19]};
    const float* bet[3] = {(const float*)d_in[16], (const float*)d_in[18], (const float*)d_in[20]};
    const float* Wc[5]  = {(const float*)d_in[21], (const float*)d_in[23], (const float*)d_in[25],
                           (const float*)d_in[27], (const float*)d_in[29]};
    const float* bc[5]  = {(const float*)d_in[22], (const float*)d_in[24], (const float*)d_in[26],
                           (const float*)d_in[28], (const float*)d_in[30]};

    const int* src = ei;
    const int* dst = ei + N_EDGES;
    float* out = (float*)d_out;

    float *isd, *big1, *big2, *csr_w, *bias512;
    uint16_t *a512hi, *a512lo, *acthi, *actlo, *xhi, *xlo, *e1hi, *e1lo, *e2hi, *e2lo, *whi, *wlo;
    int *rowstart, *cursor, *csr_src;
    cudaGetSymbolAddress((void**)&isd,  g_isd);
    cudaGetSymbolAddress((void**)&big1, g_big1);
    cudaGetSymbolAddress((void**)&big2, g_big2);
    cudaGetSymbolAddress((void**)&a512hi, g_a512hi);
    cudaGetSymbolAddress((void**)&a512lo, g_a512lo);
    cudaGetSymbolAddress((void**)&acthi, g_acthi);
    cudaGetSymbolAddress((void**)&actlo, g_actlo);
    cudaGetSymbolAddress((void**)&xhi, g_xhi);
    cudaGetSymbolAddress((void**)&xlo, g_xlo);
    cudaGetSymbolAddress((void**)&e1hi, g_e1hi);
    cudaGetSymbolAddress((void**)&e1lo, g_e1lo);
    cudaGetSymbolAddress((void**)&e2hi, g_e2hi);
    cudaGetSymbolAddress((void**)&e2lo, g_e2lo);
    cudaGetSymbolAddress((void**)&whi, g_whi);
    cudaGetSymbolAddress((void**)&wlo, g_wlo);
    cudaGetSymbolAddress((void**)&bias512, g_bias512);
    cudaGetSymbolAddress((void**)&rowstart, g_rowstart);
    cudaGetSymbolAddress((void**)&cursor,   g_cursor);
    cudaGetSymbolAddress((void**)&csr_src,  g_csr_src);
    cudaGetSymbolAddress((void**)&csr_w,    g_csr_w);
    uint16_t* big1h = (uint16_t*)big1;   // fp16 view of big1 (UV)

    // degree + CSR first (layer-1 gather needs them)
    deg_init<<<(N_NODES + 255) / 256, 256>>>(isd, N_NODES);
    deg_count<<<(N_EDGES + 255) / 256, 256>>>(dst, isd, N_EDGES);
    deg_fin<<<(N_NODES + 255) / 256, 256>>>(isd, N_NODES);
    zero_int<<<(N_NODES + 255) / 256, 256>>>(cursor, N_NODES);
    count_int<<<(N_EDGES + 255) / 256, 256>>>(dst, cursor, N_EDGES);
    scan_deg<<<1, 1024>>>(cursor, rowstart);
    zero_int<<<(N_NODES + 255) / 256, 256>>>(cursor, N_NODES);
    csr_fill<<<(N_EDGES + 255) / 256, 256>>>(src, dst, rowstart, cursor, isd, csr_src, csr_w);

    // layer-1 reorder: xa = Â x (128-wide gather, bf16 split out)
    gcn_gather_x<<<(N_NODES * 32 + 255) / 256, 256>>>(x, rowstart, csr_src, csr_w, isd,
                                                      xhi, xlo);
    pack_bias512<<<2, 256>>>(bb[0][0], bb[1][0], bias512);
    pack2<<<(128 * 512 + 255) / 256, 256>>>(W[0][0], W[1][0], whi + OFF_WN1, wlo + OFF_WN1, 128 * 512);

    // agg512 = xa @ [W11|W21] + [b11|b21]  -> big2  [bf16x3, fp32 out]
    run_gemm3(xhi, xlo, D_IN, 0, whi + OFF_WN1, wlo + OFF_WN1, bias512,
              big2, nullptr, nullptr, N_NODES, 512, D_IN, 0, 0);

    // remaining weight packing (overlaps GEMM tail)
    pack2_fp16<<<(256 * 512 + 255) / 256, 256>>>(W[0][1], W[1][1], whi + OFF_WN2, 256 * 512);
    pack2_fp16<<<(256 * 512 + 255) / 256, 256>>>(W[0][2], W[1][2], whi + OFF_WN3, 256 * 512);
    pack_wuv_fp16<<<(256 * 512 + 255) / 256, 256>>>(Wc[0], whi + OFF_WUV);
    convert_fp16<<<(65536 + 255) / 256, 256>>>(Wc[1], whi + OFF_WC2, 65536);
    convert_fp16<<<(32768 + 255) / 256, 256>>>(Wc[2], whi + OFF_WC3, 32768);
    convert_fp16<<<(8192 + 255) / 256, 256>>>(Wc[3], whi + OFF_WC4, 8192);

    const int gather_blocks = (N_NODES * 32 + 255) / 256;
    const int NH512_2 = NH512 / 2;
    const int NH2 = NH / 2;

    // layer-1 BN (stats standalone; agg already in big2) -> fp16 split
    bn_zero512<<<1, 512>>>();
    bn_stats512<<<(N_NODES + 7) / 8, 256>>>(big2);
    bn_final512<<<1, 512>>>();
    bn_apply_split512<<<(NH512_2 + 255) / 256, 256>>>(big2, gam[0], bet[0],
                                                      a512hi, a512lo, NH512_2);

    // layers 2, 3: fp16x2 GEMM -> fp32 hw -> fp32 float4 gather (fused stats)
    const int woffN[2] = {OFF_WN2, OFF_WN3};
    for (int li = 1; li < 3; ++li) {
        run_gemm2(a512hi, a512lo, 512, 1, whi + woffN[li - 1], nullptr,
                  big1, nullptr, nullptr, N_NODES, 512, H, 0, 0);
        bn_zero512<<<1, 512>>>();
        gcn_gather512<<<gather_blocks, 256>>>(big1, rowstart, csr_src, csr_w, isd,
                                              bb[0][li], bb[1][li], big2);
        bn_final512<<<1, 512>>>();
        if (li < 2)
            bn_apply_split512<<<(NH512_2 + 255) / 256, 256>>>(big2, gam[li], bet[li],
                                                              a512hi, a512lo, NH512_2);
        else
            bn_add_convert<<<(NH2 + 255) / 256, 256>>>(big2, gam[li], bet[li],
                                                       acthi, actlo, NH2);
    }

    // U||V: [50k,256] @ [256,512] -> big1 (UV fp16)  [fp16x2, fp16 out]
    run_gemm2(acthi, actlo, H, 0, whi + OFF_WUV, nullptr,
              nullptr, big1h, nullptr, N_NODES, 512, H, 0, 3);
    edge_l1<<<(N_EDGES * 32 + 255) / 256, 256>>>((const __half*)big1h, attr,
                                                 Wc[0] + 512 * 256, bc[0],
                                                 src, dst, e1hi, e1lo);

    // edge MLP [fp16x2]
    run_gemm2(e1hi, e1lo, 256, 0, whi + OFF_WC2, bc[1],
              nullptr, e2hi, e2lo, N_EDGES, 256, 256, 1, 1);
    run_gemm2(e2hi, e2lo, 256, 0, whi + OFF_WC3, bc[2],
              nullptr, e1hi, e1lo, N_EDGES, 128, 256, 1, 1);
    // Wc4 + fused final 64->2 (out written directly)
    run_gemm_final(e1hi, e1lo, 128, whi + OFF_WC4, bc[3], Wc[4], bc[4], out,
                   N_EDGES, 128);
}